// round 9
// baseline (speedup 1.0000x reference)
#include <cuda_runtime.h>
#include <cstdint>

// 2D acoustic FDTD, 4 shots x 512 steps, 256x256 grid.
// One cluster per shot, CSZ CTAs x 1024 threads. 128 column-PAIR threads x
// NG row groups; packed f32x2 math (FFMA2). p_t / -p_{t-1} pairs in
// registers; smem mirror gives left/right + seams + halos. Halo rows pushed
// with st.async.b64 + parity mbarriers, BOUNDARY-FIRST. Global CTA barrier
// replaced by PAIRWISE named barriers between adjacent row groups (elastic
// wavefront); receiver samples stored register-direct by owning threads.

#define NS    4
#define NT    512
#define NZ    256
#define NX    256
#define NR    128
#define S     260          // padded row stride: cols [2..257] live, pads 0
#define NG    8            // row groups (1024 threads / 128 col-pairs)

typedef unsigned long long u64;

__device__ __forceinline__ uint32_t smem_u32(const void* p) {
    uint32_t a;
    asm("{ .reg .u64 t; cvta.to.shared.u64 t, %1; cvt.u32.u64 %0, t; }"
        : "=r"(a) : "l"(p));
    return a;
}
__device__ __forceinline__ uint32_t mapa32(uint32_t laddr, uint32_t rank) {
    uint32_t ra;
    asm("mapa.shared::cluster.u32 %0, %1, %2;" : "=r"(ra) : "r"(laddr), "r"(rank));
    return ra;
}
__device__ __forceinline__ void mbar_init(uint32_t mbar, uint32_t cnt) {
    asm volatile("mbarrier.init.shared::cta.b64 [%0], %1;" :: "r"(mbar), "r"(cnt) : "memory");
}
__device__ __forceinline__ void mbar_expect(uint32_t mbar, uint32_t tx) {
    asm volatile("mbarrier.arrive.expect_tx.shared::cta.b64 _, [%0], %1;"
                 :: "r"(mbar), "r"(tx) : "memory");
}
__device__ __forceinline__ void mbar_wait(uint32_t mbar, uint32_t parity) {
    asm volatile(
        "{\n\t"
        ".reg .pred P;\n\t"
        "LW%=:\n\t"
        "mbarrier.try_wait.parity.acquire.cluster.shared::cta.b64 P, [%0], %1;\n\t"
        "@P bra LD%=;\n\t"
        "bra LW%=;\n\t"
        "LD%=:\n\t"
        "}"
        :: "r"(mbar), "r"(parity) : "memory");
}
__device__ __forceinline__ void st_async_f2(uint32_t rslot, uint32_t rmbar, u64 v) {
    asm volatile("st.async.shared::cluster.mbarrier::complete_tx::bytes.b64 [%0], %1, [%2];"
                 :: "r"(rslot), "l"(v), "r"(rmbar) : "memory");
}
__device__ __forceinline__ void cluster_sync_() {
    asm volatile("barrier.cluster.arrive.aligned;" ::: "memory");
    asm volatile("barrier.cluster.wait.aligned;" ::: "memory");
}
__device__ __forceinline__ void bar_named(int id) {
    asm volatile("bar.sync %0, 256;" :: "r"(id) : "memory");
}

// ---- packed f32x2 helpers ----
__device__ __forceinline__ u64 f2pack(float lo, float hi) {
    u64 r; asm("mov.b64 %0, {%1, %2};" : "=l"(r) : "f"(lo), "f"(hi)); return r;
}
__device__ __forceinline__ void f2unpack(u64 v, float& lo, float& hi) {
    asm("mov.b64 {%0, %1}, %2;" : "=f"(lo), "=f"(hi) : "l"(v));
}
__device__ __forceinline__ u64 f2add(u64 a, u64 b) {
    u64 r; asm("add.rn.f32x2 %0, %1, %2;" : "=l"(r) : "l"(a), "l"(b)); return r;
}
__device__ __forceinline__ u64 f2mul(u64 a, u64 b) {
    u64 r; asm("mul.rn.f32x2 %0, %1, %2;" : "=l"(r) : "l"(a), "l"(b)); return r;
}
__device__ __forceinline__ u64 f2fma(u64 a, u64 b, u64 c) {
    u64 r; asm("fma.rn.f32x2 %0, %1, %2, %3;" : "=l"(r) : "l"(a), "l"(b), "l"(c)); return r;
}
__device__ __forceinline__ u64 f2ld(const float* p) {        // aligned LDS.64
    float2 v = *(const float2*)p; return f2pack(v.x, v.y);
}
__device__ __forceinline__ void f2st(float* p, u64 v) {      // aligned STS.64
    float lo, hi; f2unpack(v, lo, hi);
    *(float2*)p = make_float2(lo, hi);
}

template<int CSZ>
__global__ void __launch_bounds__(1024, 1) __cluster_dims__(CSZ, 1, 1)
wave_kernel(const float* __restrict__ xin,   // (NS, NT)
            const float* __restrict__ vp,    // (NZ, NX)
            const int*   __restrict__ src_z, // (NS,)
            const int*   __restrict__ src_x, // (NS,)
            const int*   __restrict__ rec_z, // (NS, NR)
            const int*   __restrict__ rec_x, // (NS, NR)
            float*       __restrict__ out)   // (NS, NT, NR, 1)
{
    constexpr int RPC  = NZ / CSZ;      // rows per CTA
    constexpr int RPT  = RPC / NG;      // rows per thread
    constexpr int ROWS = RPC + 2;       // + halo rows 0 and ROWS-1
    extern __shared__ float smem[];     // [2][ROWS][S]
    __shared__ __align__(8) uint64_t mbars[4];  // [0/1]=top par, [2/3]=bot par
    __shared__ int rhead[NG * 128];     // per-thread receiver list head (-1)
    __shared__ int rnext[NR];
    __shared__ int rinfo[NR];           // zloc | lane<<2

    const int tid = threadIdx.x;
    const int g   = tid >> 7;           // row group
    const int tx  = tid & 127;          // column-pair index
    const int xi  = 2 + 2 * tx;         // first element col of pair
    const int s   = blockIdx.x / CSZ;   // shot
    uint32_t rank;
    asm("mov.u32 %0, %%cluster_ctarank;" : "=r"(rank));
    const int r0  = (int)rank * RPC;
    const int gz0 = g * RPT;

    for (int i = tid; i < 2 * ROWS * S; i += 1024) smem[i] = 0.0f;
    rhead[tid] = -1;
    if (tid == 0)
        for (int i = 0; i < 4; i++) mbar_init(smem_u32(&mbars[i]), 1);
    __syncthreads();
    cluster_sync_();                    // mbars initialized cluster-wide

    // build per-owner receiver lists (register-direct stores later)
    if (tid < NR) {
        int rz = rec_z[s * NR + tid];
        if (rz >= r0 && rz < r0 + RPC) {
            int rx    = rec_x[s * NR + tid];
            int zc    = rz - r0;
            int owner = (zc / RPT) * 128 + (rx >> 1);
            rinfo[tid] = (zc % RPT) | ((rx & 1) << 2);
            rnext[tid] = atomicExch(&rhead[owner], tid);
        }
    }

    const int  srcz    = src_z[s];
    const int  srcx    = src_x[s];
    const int  szc     = srcz - r0;
    const bool my_src  = (szc >= gz0 && szc < gz0 + RPT) && (tx == (srcx >> 1));
    const int  szl     = szc - gz0;
    const int  srclane = srcx & 1;

    u64 c2p[RPT], ccp[RPT], nco[RPT];
#pragma unroll
    for (int z = 0; z < RPT; z++) {
        float a0 = vp[(r0 + gz0 + z) * NX + 2 * tx]     * 0.001f;
        float a1 = vp[(r0 + gz0 + z) * NX + 2 * tx + 1] * 0.001f;
        c2p[z] = f2pack((a0 * a0) * 0.01f, (a1 * a1) * 0.01f);
        ccp[z] = 0ull;
        nco[z] = 0ull;                  // -p_{t-1}
    }
    __syncthreads();                    // receiver lists final

    const int    myhead = rhead[tid];
    float* const outS   = out + (size_t)s * NT * NR;

    float* const b0 = smem;
    float* const b1 = smem + ROWS * S;
    const uint32_t base0 = smem_u32(b0);
    const uint32_t base1 = smem_u32(b1);
    const uint32_t mb_top[2] = { smem_u32(&mbars[0]), smem_u32(&mbars[1]) };
    const uint32_t mb_bot[2] = { smem_u32(&mbars[2]), smem_u32(&mbars[3]) };
    const bool has_up = (rank > 0);
    const bool has_dn = (rank < CSZ - 1);
    const bool gtop   = (g == 0);
    const bool gbot   = (g == NG - 1);
    const bool lead_t = (tid == 0);             // g0 leader (top direction)
    const bool lead_b = (tid == (NG - 1) * 128);// g7 leader (bottom direction)

    const u64 NEG4 = f2pack(-4.0f, -4.0f);
    const u64 TWO  = f2pack( 2.0f,  2.0f);
    const u64 NEG1 = f2pack(-1.0f, -1.0f);

    const int off0  = (gz0 + 1) * S + xi;
    const int offSB = gz0 * S + xi;
    const int offSA = (gz0 + RPT + 1) * S + xi;

#define STEP_ROW(PN, z, below, above, oldcc, val)                              \
    {                                                                          \
        u64 cc = ccp[z];                                                       \
        float clo, chi; f2unpack(cc, clo, chi);                                \
        u64 vert = f2add(below, above);                                        \
        u64 horz = f2add(f2pack(lv[z], clo), f2pack(chi, rv[z]));              \
        u64 sum  = f2add(vert, horz);                                          \
        u64 lap  = f2fma(cc, NEG4, sum);                                       \
        u64 tmp  = f2fma(cc, TWO, nco[z]);                                     \
        val = f2fma(c2p[z], lap, tmp);                                         \
        nco[z] = f2mul(cc, NEG1);                                              \
        if (my_src && (z) == szl) {                                            \
            float a, b; f2unpack(val, a, b);                                   \
            if (srclane) b += srcval; else a += srcval;                        \
            val = f2pack(a, b);                                                \
        }                                                                      \
        ccp[z] = val;                                                          \
        f2st((PN) + off0 + (z) * S, val);                                      \
        oldcc = cc;                                                            \
    }

// One full phase, boundary-first, pairwise barriers.
#define DO_STEP(PCUR, PNXT, RBASE, PAR, T, WAITOK, WPAR)                       \
    {                                                                          \
        float srcval = 0.0f;                                                   \
        if (my_src) srcval = (__ldg(&xin[s * NT + (T)]) * 0.001f) * 0.001f;    \
        float lv[RPT], rv[RPT];                                                \
        _Pragma("unroll")                                                      \
        for (int z = 0; z < RPT; z++) {                                        \
            float2 a = *(const float2*)((PCUR) + off0 + z * S - 2);            \
            float2 b = *(const float2*)((PCUR) + off0 + z * S + 2);            \
            lv[z] = a.y; rv[z] = b.x;                                          \
        }                                                                      \
        u64 oldcc, val;                                                        \
        if (gtop) {                                                            \
            if (lead_t && has_up) mbar_expect(mb_top[PAR], NX * 4);            \
            const u64 seamA = f2ld((PCUR) + offSA);                            \
            const u64 save0 = ccp[0];                                          \
            const u64 save1 = ccp[1];                                          \
            if (has_up && (WAITOK)) mbar_wait(mb_top[(PAR) ^ 1], (WPAR));      \
            {   /* boundary row 0 first, push immediately */                   \
                const u64 haloB = f2ld((PCUR) + offSB);                        \
                STEP_ROW(PNXT, 0, haloB, save1, oldcc, val);                   \
                if (has_up) {                                                  \
                    uint32_t rs = mapa32((RBASE) +                             \
                        (uint32_t)((ROWS - 1) * S + xi) * 4u, rank - 1);       \
                    uint32_t rm = mapa32(mb_bot[PAR], rank - 1);               \
                    st_async_f2(rs, rm, val);                                  \
                }                                                              \
            }                                                                  \
            u64 below = save0;                                                 \
            _Pragma("unroll")                                                  \
            for (int z = 1; z < RPT; z++) {                                    \
                u64 above = (z == RPT - 1) ? seamA : ccp[z + 1];               \
                STEP_ROW(PNXT, z, below, above, oldcc, val);                   \
                below = oldcc;                                                 \
            }                                                                  \
        } else if (gbot) {                                                     \
            if (lead_b && has_dn) mbar_expect(mb_bot[PAR], NX * 4);            \
            const u64 seamB = f2ld((PCUR) + offSB);                            \
            const u64 saveL = ccp[RPT - 1];                                    \
            u64 belowB = ccp[RPT - 2];                                         \
            if (has_dn && (WAITOK)) mbar_wait(mb_bot[(PAR) ^ 1], (WPAR));      \
            {   /* boundary row RPT-1 first, push immediately */               \
                const u64 haloA = f2ld((PCUR) + offSA);                        \
                STEP_ROW(PNXT, RPT - 1, belowB, haloA, oldcc, val);            \
                if (has_dn) {                                                  \
                    uint32_t rs = mapa32((RBASE) + (uint32_t)(xi) * 4u,        \
                                         rank + 1);                            \
                    uint32_t rm = mapa32(mb_top[PAR], rank + 1);               \
                    st_async_f2(rs, rm, val);                                  \
                }                                                              \
            }                                                                  \
            u64 below = seamB;                                                 \
            _Pragma("unroll")                                                  \
            for (int z = 0; z < RPT - 1; z++) {                                \
                u64 above = (z == RPT - 2) ? saveL : ccp[z + 1];               \
                STEP_ROW(PNXT, z, below, above, oldcc, val);                   \
                below = oldcc;                                                 \
            }                                                                  \
        } else {                                                               \
            const u64 seamA = f2ld((PCUR) + offSA);                            \
            u64 below = f2ld((PCUR) + offSB);                                  \
            _Pragma("unroll")                                                  \
            for (int z = 0; z < RPT; z++) {                                    \
                u64 above = (z == RPT - 1) ? seamA : ccp[z + 1];               \
                STEP_ROW(PNXT, z, below, above, oldcc, val);                   \
                below = oldcc;                                                 \
            }                                                                  \
        }                                                                      \
        /* register-direct receiver stores (owners only) */                    \
        {                                                                      \
            int e = myhead;                                                    \
            while (e >= 0) {                                                   \
                int info = rinfo[e];                                           \
                int zl = info & 3;                                             \
                u64 v = ccp[0];                                                \
                _Pragma("unroll")                                              \
                for (int z = 1; z < RPT; z++) if (zl == z) v = ccp[z];         \
                float lo, hi; f2unpack(v, lo, hi);                             \
                outS[(T) * NR + e] = (info & 4) ? hi : lo;                     \
                e = rnext[e];                                                  \
            }                                                                  \
        }                                                                      \
        /* pairwise barriers: lower id first */                                \
        if (!gtop) bar_named(g);                                               \
        if (!gbot) bar_named(g + 1);                                           \
    }

    for (int t = 0; t < NT; t += 2) {
        const uint32_t m = (uint32_t)(t >> 1);
        // step A: t even, par=0, pcur=b0 -> pnxt=b1
        DO_STEP(b0, b1, base1, 0, t, t > 0, (m - 1) & 1);
        // step B: t+1 odd, par=1, pcur=b1 -> pnxt=b0
        DO_STEP(b1, b0, base0, 1, t + 1, true, m & 1);
    }

    // drain final phase so no st.async targets our smem after exit
    if (lead_t && has_up) mbar_wait(mb_top[(NT - 1) & 1], ((NT - 1) >> 1) & 1);
    if (lead_b && has_dn) mbar_wait(mb_bot[(NT - 1) & 1], ((NT - 1) >> 1) & 1);
    __syncthreads();
    cluster_sync_();
#undef DO_STEP
#undef STEP_ROW
}

template<int CSZ>
static void launch_variant(const float* x, const float* vp, const int* sz,
                           const int* sx, const int* rz, const int* rx, float* out)
{
    const int smemb = 2 * (NZ / CSZ + 2) * S * (int)sizeof(float);
    cudaFuncSetAttribute(wave_kernel<CSZ>,
                         cudaFuncAttributeMaxDynamicSharedMemorySize, smemb);
    wave_kernel<CSZ><<<NS * CSZ, 1024, smemb>>>(x, vp, sz, sx, rz, rx, out);
}

extern "C" void kernel_launch(void* const* d_in, const int* in_sizes, int n_in,
                              void* d_out, int out_size)
{
    const float* x     = (const float*)d_in[0];
    const float* vp    = (const float*)d_in[1];
    const int*   src_z = (const int*)d_in[2];
    const int*   src_x = (const int*)d_in[3];
    const int*   rec_z = (const int*)d_in[4];
    const int*   rec_x = (const int*)d_in[5];
    float*       out   = (float*)d_out;

    const int smem16 = 2 * (NZ / 16 + 2) * S * (int)sizeof(float);
    bool use16 = false;
    if (cudaFuncSetAttribute(wave_kernel<16>,
            cudaFuncAttributeNonPortableClusterSizeAllowed, 1) == cudaSuccess &&
        cudaFuncSetAttribute(wave_kernel<16>,
            cudaFuncAttributeMaxDynamicSharedMemorySize, smem16) == cudaSuccess) {
        cudaLaunchConfig_t cfg = {};
        cfg.gridDim  = dim3(NS * 16, 1, 1);
        cfg.blockDim = dim3(1024, 1, 1);
        cfg.dynamicSmemBytes = (size_t)smem16;
        cudaLaunchAttribute attr[1];
        attr[0].id = cudaLaunchAttributeClusterDimension;
        attr[0].val.clusterDim = {16, 1, 1};
        cfg.attrs = attr;
        cfg.numAttrs = 1;
        int ncl = 0;
        if (cudaOccupancyMaxActiveClusters(&ncl, wave_kernel<16>, &cfg) == cudaSuccess
            && ncl >= NS) use16 = true;
        else cudaGetLastError();
    } else {
        cudaGetLastError();
    }

    if (use16) launch_variant<16>(x, vp, src_z, src_x, rec_z, rec_x, out);
    else       launch_variant<8>(x, vp, src_z, src_x, rec_z, rec_x, out);
}

// round 10
// speedup vs baseline: 1.0708x; 1.0708x over previous
#include <cuda_runtime.h>
#include <cstdint>

// 2D acoustic FDTD, 4 shots x 512 steps, 256x256 grid.
// One cluster per shot, CSZ CTAs x 1024 threads. 128 column-PAIR threads x
// NG row groups; packed f32x2 math (FFMA2). p_t / -p_{t-1} pairs in
// registers; smem mirror gives left/right + seams + halos. Halo rows pushed
// with st.async.b64 + parity mbarriers, BOUNDARY-FIRST. Single full-CTA
// barrier per step (cheapest on sm_103a). Time loop unrolled x4 with
// compile-time mbar parities; scalar-FADD horizontal halves.

#define NS    4
#define NT    512
#define NZ    256
#define NX    256
#define NR    128
#define S     260          // padded row stride: cols [2..257] live, pads 0
#define NG    8            // row groups (1024 threads / 128 col-pairs)

typedef unsigned long long u64;

__device__ __forceinline__ uint32_t smem_u32(const void* p) {
    uint32_t a;
    asm("{ .reg .u64 t; cvta.to.shared.u64 t, %1; cvt.u32.u64 %0, t; }"
        : "=r"(a) : "l"(p));
    return a;
}
__device__ __forceinline__ uint32_t mapa32(uint32_t laddr, uint32_t rank) {
    uint32_t ra;
    asm("mapa.shared::cluster.u32 %0, %1, %2;" : "=r"(ra) : "r"(laddr), "r"(rank));
    return ra;
}
__device__ __forceinline__ void mbar_init(uint32_t mbar, uint32_t cnt) {
    asm volatile("mbarrier.init.shared::cta.b64 [%0], %1;" :: "r"(mbar), "r"(cnt) : "memory");
}
__device__ __forceinline__ void mbar_expect(uint32_t mbar, uint32_t tx) {
    asm volatile("mbarrier.arrive.expect_tx.shared::cta.b64 _, [%0], %1;"
                 :: "r"(mbar), "r"(tx) : "memory");
}
__device__ __forceinline__ void mbar_wait(uint32_t mbar, uint32_t parity) {
    asm volatile(
        "{\n\t"
        ".reg .pred P;\n\t"
        "LW%=:\n\t"
        "mbarrier.try_wait.parity.acquire.cluster.shared::cta.b64 P, [%0], %1;\n\t"
        "@P bra LD%=;\n\t"
        "bra LW%=;\n\t"
        "LD%=:\n\t"
        "}"
        :: "r"(mbar), "r"(parity) : "memory");
}
__device__ __forceinline__ void st_async_f2(uint32_t rslot, uint32_t rmbar, u64 v) {
    asm volatile("st.async.shared::cluster.mbarrier::complete_tx::bytes.b64 [%0], %1, [%2];"
                 :: "r"(rslot), "l"(v), "r"(rmbar) : "memory");
}
__device__ __forceinline__ void cluster_sync_() {
    asm volatile("barrier.cluster.arrive.aligned;" ::: "memory");
    asm volatile("barrier.cluster.wait.aligned;" ::: "memory");
}

// ---- packed f32x2 helpers ----
__device__ __forceinline__ u64 f2pack(float lo, float hi) {
    u64 r; asm("mov.b64 %0, {%1, %2};" : "=l"(r) : "f"(lo), "f"(hi)); return r;
}
__device__ __forceinline__ void f2unpack(u64 v, float& lo, float& hi) {
    asm("mov.b64 {%0, %1}, %2;" : "=f"(lo), "=f"(hi) : "l"(v));
}
__device__ __forceinline__ u64 f2add(u64 a, u64 b) {
    u64 r; asm("add.rn.f32x2 %0, %1, %2;" : "=l"(r) : "l"(a), "l"(b)); return r;
}
__device__ __forceinline__ u64 f2mul(u64 a, u64 b) {
    u64 r; asm("mul.rn.f32x2 %0, %1, %2;" : "=l"(r) : "l"(a), "l"(b)); return r;
}
__device__ __forceinline__ u64 f2fma(u64 a, u64 b, u64 c) {
    u64 r; asm("fma.rn.f32x2 %0, %1, %2, %3;" : "=l"(r) : "l"(a), "l"(b), "l"(c)); return r;
}
__device__ __forceinline__ u64 f2ld(const float* p) {        // aligned LDS.64
    float2 v = *(const float2*)p; return f2pack(v.x, v.y);
}
__device__ __forceinline__ void f2st(float* p, u64 v) {      // aligned STS.64
    float lo, hi; f2unpack(v, lo, hi);
    *(float2*)p = make_float2(lo, hi);
}

template<int CSZ>
__global__ void __launch_bounds__(1024, 1) __cluster_dims__(CSZ, 1, 1)
wave_kernel(const float* __restrict__ xin,   // (NS, NT)
            const float* __restrict__ vp,    // (NZ, NX)
            const int*   __restrict__ src_z, // (NS,)
            const int*   __restrict__ src_x, // (NS,)
            const int*   __restrict__ rec_z, // (NS, NR)
            const int*   __restrict__ rec_x, // (NS, NR)
            float*       __restrict__ out)   // (NS, NT, NR, 1)
{
    constexpr int RPC  = NZ / CSZ;      // rows per CTA
    constexpr int RPT  = RPC / NG;      // rows per thread
    constexpr int ROWS = RPC + 2;       // + halo rows 0 and ROWS-1
    extern __shared__ float smem[];     // [2][ROWS][S]
    __shared__ __align__(8) uint64_t mbars[4];  // [0/1]=top par, [2/3]=bot par
    __shared__ int   rcnt;
    __shared__ int   rpos[NR];
    __shared__ short rid[NR];

    const int tid = threadIdx.x;
    const int g   = tid >> 7;           // row group
    const int tx  = tid & 127;          // column-pair index
    const int xi  = 2 + 2 * tx;         // first element col of pair
    const int s   = blockIdx.x / CSZ;   // shot
    uint32_t rank;
    asm("mov.u32 %0, %%cluster_ctarank;" : "=r"(rank));
    const int r0  = (int)rank * RPC;
    const int gz0 = g * RPT;

    for (int i = tid; i < 2 * ROWS * S; i += 1024) smem[i] = 0.0f;
    if (tid == 0) {
        rcnt = 0;
        for (int i = 0; i < 4; i++) mbar_init(smem_u32(&mbars[i]), 1);
    }
    __syncthreads();
    cluster_sync_();                    // mbars initialized cluster-wide

    if (tid < NR) {
        int rz = rec_z[s * NR + tid];
        if (rz >= r0 && rz < r0 + RPC) {
            int i = atomicAdd(&rcnt, 1);
            rpos[i] = (rz - r0 + 1) * S + rec_x[s * NR + tid] + 2;
            rid[i]  = (short)tid;
        }
    }

    const int  srcz    = src_z[s];
    const int  srcx    = src_x[s];
    const int  szc     = srcz - r0;
    const bool my_src  = (szc >= gz0 && szc < gz0 + RPT) && (tx == (srcx >> 1));
    const int  szl     = szc - gz0;
    const int  srclane = srcx & 1;

    u64 c2p[RPT], ccp[RPT], nco[RPT];
#pragma unroll
    for (int z = 0; z < RPT; z++) {
        float a0 = vp[(r0 + gz0 + z) * NX + 2 * tx]     * 0.001f;
        float a1 = vp[(r0 + gz0 + z) * NX + 2 * tx + 1] * 0.001f;
        c2p[z] = f2pack((a0 * a0) * 0.01f, (a1 * a1) * 0.01f);
        ccp[z] = 0ull;
        nco[z] = 0ull;                  // -p_{t-1}
    }
    __syncthreads();                    // rcnt/rpos/rid final

    // hoist receiver bookkeeping into registers
    const bool has_rec = (tid < rcnt);
    const int  myrpos  = has_rec ? rpos[tid] : 0;
    float*     outp    = out + (size_t)s * NT * NR + (has_rec ? (int)rid[tid] : 0);

    float* const b0 = smem;
    float* const b1 = smem + ROWS * S;
    const uint32_t base0 = smem_u32(b0);
    const uint32_t base1 = smem_u32(b1);
    const uint32_t mb_top[2] = { smem_u32(&mbars[0]), smem_u32(&mbars[1]) };
    const uint32_t mb_bot[2] = { smem_u32(&mbars[2]), smem_u32(&mbars[3]) };
    const bool has_up = (rank > 0);
    const bool has_dn = (rank < CSZ - 1);
    const bool gtop   = (g == 0);
    const bool gbot   = (g == NG - 1);
    const bool lead_t = (tid == 0);              // g0 leader: top direction
    const bool lead_b = (tid == (NG - 1) * 128); // g_last leader: bottom dir

    const u64 NEG4 = f2pack(-4.0f, -4.0f);
    const u64 TWO  = f2pack( 2.0f,  2.0f);
    const u64 NEG1 = f2pack(-1.0f, -1.0f);

    const int off0  = (gz0 + 1) * S + xi;
    const int offSB = gz0 * S + xi;
    const int offSA = (gz0 + RPT + 1) * S + xi;

// one row update; horizontal halves as scalar FADDs into the result pair.
#define STEP_ROW(PN, z, below, above, oldcc, val)                              \
    {                                                                          \
        u64 cc = ccp[z];                                                       \
        float clo, chi; f2unpack(cc, clo, chi);                                \
        u64 vert = f2add(below, above);                                        \
        u64 horz = f2pack(lv[z] + chi, clo + rv[z]);                           \
        u64 lap  = f2fma(cc, NEG4, f2add(vert, horz));                         \
        u64 tmp  = f2fma(cc, TWO, nco[z]);                                     \
        val = f2fma(c2p[z], lap, tmp);                                         \
        nco[z] = f2mul(cc, NEG1);                                              \
        if (my_src && (z) == szl) {                                            \
            float a, b; f2unpack(val, a, b);                                   \
            if (srclane) b += srcval; else a += srcval;                        \
            val = f2pack(a, b);                                                \
        }                                                                      \
        ccp[z] = val;                                                          \
        f2st((PN) + off0 + (z) * S, val);                                      \
        oldcc = cc;                                                            \
    }

// One full phase, boundary-first, single full-CTA barrier.
// PAR/WPAR are compile-time literals per position in the x4 unroll.
#define DO_STEP(PCUR, PNXT, RBASE, PAR, T, WAITOK, WPAR, OUTOFF)               \
    {                                                                          \
        float srcval = 0.0f;                                                   \
        if (my_src) srcval = (__ldg(&xin[s * NT + (T)]) * 0.001f) * 0.001f;    \
        float lv[RPT], rv[RPT];                                                \
        _Pragma("unroll")                                                      \
        for (int z = 0; z < RPT; z++) {                                        \
            float2 a = *(const float2*)((PCUR) + off0 + z * S - 2);            \
            float2 b = *(const float2*)((PCUR) + off0 + z * S + 2);            \
            lv[z] = a.y; rv[z] = b.x;                                          \
        }                                                                      \
        u64 oldcc, val;                                                        \
        if (gtop) {                                                            \
            if (lead_t && has_up) mbar_expect(mb_top[PAR], NX * 4);            \
            const u64 seamA = f2ld((PCUR) + offSA);                            \
            const u64 save0 = ccp[0];                                          \
            const u64 save1 = ccp[1];                                          \
            if (has_up && (WAITOK)) mbar_wait(mb_top[(PAR) ^ 1], (WPAR));      \
            {   /* boundary row 0 first, push immediately */                   \
                const u64 haloB = f2ld((PCUR) + offSB);                        \
                STEP_ROW(PNXT, 0, haloB, save1, oldcc, val);                   \
                if (has_up) {                                                  \
                    uint32_t rs = mapa32((RBASE) +                             \
                        (uint32_t)((ROWS - 1) * S + xi) * 4u, rank - 1);       \
                    uint32_t rm = mapa32(mb_bot[PAR], rank - 1);               \
                    st_async_f2(rs, rm, val);                                  \
                }                                                              \
            }                                                                  \
            u64 below = save0;                                                 \
            _Pragma("unroll")                                                  \
            for (int z = 1; z < RPT; z++) {                                    \
                u64 above = (z == RPT - 1) ? seamA : ccp[z + 1];               \
                STEP_ROW(PNXT, z, below, above, oldcc, val);                   \
                below = oldcc;                                                 \
            }                                                                  \
        } else if (gbot) {                                                     \
            if (lead_b && has_dn) mbar_expect(mb_bot[PAR], NX * 4);            \
            const u64 seamB = f2ld((PCUR) + offSB);                            \
            const u64 saveL = ccp[RPT - 1];                                    \
            u64 belowB = ccp[RPT - 2];                                         \
            if (has_dn && (WAITOK)) mbar_wait(mb_bot[(PAR) ^ 1], (WPAR));      \
            {   /* boundary row RPT-1 first, push immediately */               \
                const u64 haloA = f2ld((PCUR) + offSA);                        \
                STEP_ROW(PNXT, RPT - 1, belowB, haloA, oldcc, val);            \
                if (has_dn) {                                                  \
                    uint32_t rs = mapa32((RBASE) + (uint32_t)(xi) * 4u,        \
                                         rank + 1);                            \
                    uint32_t rm = mapa32(mb_top[PAR], rank + 1);               \
                    st_async_f2(rs, rm, val);                                  \
                }                                                              \
            }                                                                  \
            u64 below = seamB;                                                 \
            _Pragma("unroll")                                                  \
            for (int z = 0; z < RPT - 1; z++) {                                \
                u64 above = (z == RPT - 2) ? saveL : ccp[z + 1];               \
                STEP_ROW(PNXT, z, below, above, oldcc, val);                   \
                below = oldcc;                                                 \
            }                                                                  \
        } else {                                                               \
            const u64 seamA = f2ld((PCUR) + offSA);                            \
            u64 below = f2ld((PCUR) + offSB);                                  \
            _Pragma("unroll")                                                  \
            for (int z = 0; z < RPT; z++) {                                    \
                u64 above = (z == RPT - 1) ? seamA : ccp[z + 1];               \
                STEP_ROW(PNXT, z, below, above, oldcc, val);                   \
                below = oldcc;                                                 \
            }                                                                  \
        }                                                                      \
        __syncthreads();                                                       \
        if (has_rec) outp[OUTOFF] = (PNXT)[myrpos];                            \
    }

    // x4 unroll: phases t mod 4 -> (PAR, WPAR) = (0,1),(1,0),(0,0),(1,1)
    for (int t = 0; t < NT; t += 4) {
        DO_STEP(b0, b1, base1, 0, t,     t > 0, 1, 0);
        DO_STEP(b1, b0, base0, 1, t + 1, true,  0, NR);
        DO_STEP(b0, b1, base1, 0, t + 2, true,  0, 2 * NR);
        DO_STEP(b1, b0, base0, 1, t + 3, true,  1, 3 * NR);
        outp += 4 * NR;
    }

    // drain final phase (NT-1 = 511: mbar[1], parity 1)
    if (lead_t && has_up) mbar_wait(mb_top[1], 1);
    if (lead_b && has_dn) mbar_wait(mb_bot[1], 1);
    __syncthreads();
    cluster_sync_();
#undef DO_STEP
#undef STEP_ROW
}

template<int CSZ>
static void launch_variant(const float* x, const float* vp, const int* sz,
                           const int* sx, const int* rz, const int* rx, float* out)
{
    const int smemb = 2 * (NZ / CSZ + 2) * S * (int)sizeof(float);
    cudaFuncSetAttribute(wave_kernel<CSZ>,
                         cudaFuncAttributeMaxDynamicSharedMemorySize, smemb);
    wave_kernel<CSZ><<<NS * CSZ, 1024, smemb>>>(x, vp, sz, sx, rz, rx, out);
}

extern "C" void kernel_launch(void* const* d_in, const int* in_sizes, int n_in,
                              void* d_out, int out_size)
{
    const float* x     = (const float*)d_in[0];
    const float* vp    = (const float*)d_in[1];
    const int*   src_z = (const int*)d_in[2];
    const int*   src_x = (const int*)d_in[3];
    const int*   rec_z = (const int*)d_in[4];
    const int*   rec_x = (const int*)d_in[5];
    float*       out   = (float*)d_out;

    const int smem16 = 2 * (NZ / 16 + 2) * S * (int)sizeof(float);
    bool use16 = false;
    if (cudaFuncSetAttribute(wave_kernel<16>,
            cudaFuncAttributeNonPortableClusterSizeAllowed, 1) == cudaSuccess &&
        cudaFuncSetAttribute(wave_kernel<16>,
            cudaFuncAttributeMaxDynamicSharedMemorySize, smem16) == cudaSuccess) {
        cudaLaunchConfig_t cfg = {};
        cfg.gridDim  = dim3(NS * 16, 1, 1);
        cfg.blockDim = dim3(1024, 1, 1);
        cfg.dynamicSmemBytes = (size_t)smem16;
        cudaLaunchAttribute attr[1];
        attr[0].id = cudaLaunchAttributeClusterDimension;
        attr[0].val.clusterDim = {16, 1, 1};
        cfg.attrs = attr;
        cfg.numAttrs = 1;
        int ncl = 0;
        if (cudaOccupancyMaxActiveClusters(&ncl, wave_kernel<16>, &cfg) == cudaSuccess
            && ncl >= NS) use16 = true;
        else cudaGetLastError();
    } else {
        cudaGetLastError();
    }

    if (use16) launch_variant<16>(x, vp, src_z, src_x, rec_z, rec_x, out);
    else       launch_variant<8>(x, vp, src_z, src_x, rec_z, rec_x, out);
}